// round 2
// baseline (speedup 1.0000x reference)
#include <cuda_runtime.h>
#include <cuda_bf16.h>

#define IMG     512
#define KW      33
#define HBLK    128
#define WBLK    128
#define PATCH_H 36
#define PATCH_W 160
#define PSTRIDE 168                      // words per patch row (42 x 16B; 42 mod 8 == 2 -> conflict-free LDS.128)
#define CSTRIDE (PATCH_H * PSTRIDE)      // 6048 words per channel
#define WBC     32                       // kernel-blocks per CTA (x direction)
#define CHUNK_U 4                        // K rows staged per double-buffer chunk
#define KROW    36                       // padded v-stride in K smem (33 -> 36, 16B aligned)
#define KBUF_WORDS (CHUNK_U * WBC * KROW)   // 4608 words per buffer
#define SMEM_WORDS (3 * CSTRIDE + 2 * KBUF_WORDS)
#define SMEM_BYTES (SMEM_WORDS * 4)      // 109440 B

__device__ __forceinline__ unsigned smem_u32(const void* p) {
    unsigned a;
    asm("{ .reg .u64 t; cvta.to.shared.u64 t, %1; cvt.u32.u64 %0, t; }" : "=r"(a) : "l"(p));
    return a;
}

__global__ __launch_bounds__(128, 2)
void reblur_kernel(const float* __restrict__ img,
                   const float* __restrict__ Kg,
                   float* __restrict__ out)
{
    extern __shared__ float smem[];
    float* patchS = smem;                      // [3][36][PSTRIDE]
    float* Ksm0   = smem + 3 * CSTRIDE;        // [CHUNK_U][WBC][KROW]
    float* Ksm1   = Ksm0 + KBUF_WORDS;

    const int tid = threadIdx.x;
    const int oi  = tid & 3;        // intra-block output row
    const int wbc = tid >> 2;       // kernel-block within CTA (0..31)
    const int bx  = blockIdx.x;     // 0..3  (chunk of 32 wb)
    const int hb  = blockIdx.y;     // 0..127

    // ---------------- stage image patch into smem ----------------
    const int col0 = 128 * bx - 16;
    const int row0 = 4 * hb - 16;
    #pragma unroll 1
    for (int i = tid; i < 3 * PATCH_H * PATCH_W; i += 128) {
        int c   = i / (PATCH_H * PATCH_W);
        int rem = i - c * (PATCH_H * PATCH_W);
        int r   = rem / PATCH_W;
        int x   = rem - r * PATCH_W;
        int ri  = min(max(row0 + r, 0), IMG - 1);   // edge clamp == pad mode 'edge'
        int ci  = min(max(col0 + x, 0), IMG - 1);
        patchS[c * CSTRIDE + r * PSTRIDE + x] = img[(c * IMG + ri) * IMG + ci];
    }

    // ---------------- K staging: cp.async, transposed to [wb][v] ----------------
    const float* Kbase = Kg + hb * WBLK + WBC * bx;   // + uv*HBLK*WBLK + wbl
    auto stage = [&](float* dstbuf, int ubase) {
        unsigned dbase = smem_u32(dstbuf);
        #pragma unroll 1
        for (int i = tid; i < CHUNK_U * KW * WBC; i += 128) {
            int ul  = i / (KW * WBC);
            int rem = i - ul * (KW * WBC);
            int v   = rem >> 5;      // 0..32
            int wbl = rem & 31;      // coalesced: warp covers one full v row of 32 wb
            int u   = ubase + ul;
            if (u < KW) {
                const float* src = Kbase + (u * KW + v) * (HBLK * WBLK) + wbl;
                unsigned dst = dbase + 4u * ((unsigned)(ul * WBC + wbl) * KROW + v);
                asm volatile("cp.async.ca.shared.global [%0], [%1], 4;" :: "r"(dst), "l"(src));
            }
        }
        asm volatile("cp.async.commit_group;" ::: "memory");
    };

    stage(Ksm0, 0);
    asm volatile("cp.async.wait_group 0;" ::: "memory");
    __syncthreads();

    // ---------------- main compute ----------------
    float acc[3][4];
    #pragma unroll
    for (int c = 0; c < 3; ++c)
        #pragma unroll
        for (int j = 0; j < 4; ++j) acc[c][j] = 0.f;

    const int NCH = (KW + CHUNK_U - 1) / CHUNK_U;   // 9 chunks (last has 1 u-row)
    #pragma unroll 1
    for (int ch = 0; ch < NCH; ++ch) {
        float* cur = (ch & 1) ? Ksm1 : Ksm0;
        float* nxt = (ch & 1) ? Ksm0 : Ksm1;
        if (ch + 1 < NCH) stage(nxt, (ch + 1) * CHUNK_U);   // overlap next chunk's HBM loads

        const int ulim = min(CHUNK_U, KW - ch * CHUNK_U);
        #pragma unroll 1
        for (int ul = 0; ul < ulim; ++ul) {
            const int u = ch * CHUNK_U + ul;

            // K row -> registers (9x LDS.128, broadcast across oi, conflict-free)
            float kk[36];
            {
                const float4* ks = reinterpret_cast<const float4*>(cur + (ul * WBC + wbc) * KROW);
                #pragma unroll
                for (int j = 0; j < 9; ++j) {
                    float4 t = ks[j];
                    kk[4*j] = t.x; kk[4*j+1] = t.y; kk[4*j+2] = t.z; kk[4*j+3] = t.w;
                }
            }

            const int row = oi + u;
            #pragma unroll
            for (int c = 0; c < 3; ++c) {
                // patch row segment -> registers (9x LDS.128, conflict-free via PSTRIDE=168)
                float p[36];
                const float4* ps = reinterpret_cast<const float4*>(
                    patchS + c * CSTRIDE + row * PSTRIDE + 4 * wbc);
                #pragma unroll
                for (int j = 0; j < 9; ++j) {
                    float4 t = ps[j];
                    p[4*j] = t.x; p[4*j+1] = t.y; p[4*j+2] = t.z; p[4*j+3] = t.w;
                }

                float a0 = acc[c][0], a1 = acc[c][1], a2 = acc[c][2], a3 = acc[c][3];
                #pragma unroll
                for (int v = 0; v < KW; ++v) {
                    float kv = kk[v];
                    a0 = fmaf(kv, p[v],     a0);
                    a1 = fmaf(kv, p[v + 1], a1);
                    a2 = fmaf(kv, p[v + 2], a2);
                    a3 = fmaf(kv, p[v + 3], a3);
                }
                acc[c][0] = a0; acc[c][1] = a1; acc[c][2] = a2; acc[c][3] = a3;
            }
        }
        asm volatile("cp.async.wait_group 0;" ::: "memory");
        __syncthreads();
    }

    // ---------------- write output (float4 per channel) ----------------
    const int orow = 4 * hb + oi;
    const int ocol = 128 * bx + 4 * wbc;
    #pragma unroll
    for (int c = 0; c < 3; ++c) {
        float4 r = make_float4(acc[c][0], acc[c][1], acc[c][2], acc[c][3]);
        *reinterpret_cast<float4*>(out + (c * IMG + orow) * IMG + ocol) = r;
    }
}

extern "C" void kernel_launch(void* const* d_in, const int* in_sizes, int n_in,
                              void* d_out, int out_size)
{
    const float* img = (const float*)d_in[0];   // (1,3,512,512) fp32
    const float* Kg  = (const float*)d_in[1];   // (1,1089,128,128) fp32
    float* out = (float*)d_out;                 // (1,3,512,512) fp32

    cudaFuncSetAttribute(reblur_kernel,
                         cudaFuncAttributeMaxDynamicSharedMemorySize, SMEM_BYTES);
    dim3 grid(4, 128);
    reblur_kernel<<<grid, 128, SMEM_BYTES>>>(img, Kg, out);
}

// round 3
// speedup vs baseline: 1.5777x; 1.5777x over previous
#include <cuda_runtime.h>
#include <cuda_bf16.h>

#define IMG     512
#define KW      33
#define HBLK    128
#define WBLK    128
#define PATCH_H 36
#define PATCH_W 160
#define PSTRIDE 168                      // words/patch row (42x16B granules, 42 mod 8 == 2 -> conflict-free LDS.128)
#define CSTRIDE (PATCH_H * PSTRIDE)      // 6048 words per channel
#define WBC     32                       // kernel-blocks per CTA (x)
#define NG      3                        // u-split groups
#define USTEP   11                       // u's per group (3*11 = 33)
#define KROW    36                       // padded v-stride (33 -> 36)
#define KBUF_WORDS (NG * WBC * KROW)     // 3456 words per buffer (3 K-rows x 32 wb)
#define SMEM_WORDS (3 * CSTRIDE + 2 * KBUF_WORDS)
#define SMEM_BYTES (SMEM_WORDS * 4)      // 100,224 B -> 2 CTAs/SM, 24 warps/SM

__device__ __forceinline__ unsigned smem_u32(const void* p) {
    unsigned a;
    asm("{ .reg .u64 t; cvta.to.shared.u64 t, %1; cvt.u32.u64 %0, t; }" : "=r"(a) : "l"(p));
    return a;
}

__global__ __launch_bounds__(384, 2)
void reblur_kernel(const float* __restrict__ img,
                   const float* __restrict__ Kg,
                   float* __restrict__ out)
{
    extern __shared__ float smem[];
    float* patchS = smem;                      // [3][36][PSTRIDE]
    float* Ksm0   = smem + 3 * CSTRIDE;        // [NG][WBC][KROW]
    float* Ksm1   = Ksm0 + KBUF_WORDS;

    const int tid    = threadIdx.x;
    const int g      = tid >> 7;        // u-group 0..2
    const int wg_tid = tid & 127;
    const int oi     = wg_tid & 3;      // intra-block output row
    const int wbc    = wg_tid >> 2;     // kernel-block within CTA (0..31)
    const int bx     = blockIdx.x;      // 0..3
    const int hb     = blockIdx.y;      // 0..127

    // ---------------- stage image patch into smem ----------------
    const int col0 = 128 * bx - 16;
    const int row0 = 4 * hb - 16;
    #pragma unroll 1
    for (int i = tid; i < 3 * PATCH_H * PATCH_W; i += 384) {
        int c   = i / (PATCH_H * PATCH_W);
        int rem = i - c * (PATCH_H * PATCH_W);
        int r   = rem / PATCH_W;
        int x   = rem - r * PATCH_W;
        int ri  = min(max(row0 + r, 0), IMG - 1);   // edge clamp == jnp.pad mode 'edge'
        int ci  = min(max(col0 + x, 0), IMG - 1);
        patchS[c * CSTRIDE + r * PSTRIDE + x] = img[(c * IMG + ri) * IMG + ci];
    }

    // ------- K staging: rows {t, t+11, t+22}, transposed to [g][wb][v], cp.async -------
    const float* Kbase = Kg + hb * WBLK + WBC * bx;
    auto stage = [&](float* dstbuf, int t) {
        unsigned dbase = smem_u32(dstbuf);
        #pragma unroll 1
        for (int i = tid; i < NG * KW * WBC; i += 384) {   // 3168 elems
            int g2  = i / (KW * WBC);
            int rem = i - g2 * (KW * WBC);
            int v   = rem >> 5;      // 0..32
            int wbl = rem & 31;      // warp covers 32 consecutive wb -> 128B coalesced
            int u   = USTEP * g2 + t;
            const float* src = Kbase + (u * KW + v) * (HBLK * WBLK) + wbl;
            unsigned dst = dbase + 4u * ((unsigned)(g2 * WBC + wbl) * KROW + v);
            asm volatile("cp.async.ca.shared.global [%0], [%1], 4;" :: "r"(dst), "l"(src));
        }
        asm volatile("cp.async.commit_group;" ::: "memory");
    };

    stage(Ksm0, 0);
    asm volatile("cp.async.wait_group 0;" ::: "memory");
    __syncthreads();

    // ---------------- main compute: 11 steps, each group one u per step ----------------
    float acc[3][4];
    #pragma unroll
    for (int c = 0; c < 3; ++c)
        #pragma unroll
        for (int j = 0; j < 4; ++j) acc[c][j] = 0.f;

    #pragma unroll 1
    for (int t = 0; t < USTEP; ++t) {
        float* cur = (t & 1) ? Ksm1 : Ksm0;
        float* nxt = (t & 1) ? Ksm0 : Ksm1;
        if (t + 1 < USTEP) stage(nxt, t + 1);     // overlap next chunk's HBM loads

        const int u = USTEP * g + t;

        // K row -> registers (9x LDS.128, broadcast across oi lanes, conflict-free)
        float kk[36];
        {
            const float4* ks = reinterpret_cast<const float4*>(cur + (g * WBC + wbc) * KROW);
            #pragma unroll
            for (int j = 0; j < 9; ++j) {
                float4 v4 = ks[j];
                kk[4*j] = v4.x; kk[4*j+1] = v4.y; kk[4*j+2] = v4.z; kk[4*j+3] = v4.w;
            }
        }

        const int row = oi + u;
        #pragma unroll
        for (int c = 0; c < 3; ++c) {
            float p[36];
            const float4* ps = reinterpret_cast<const float4*>(
                patchS + c * CSTRIDE + row * PSTRIDE + 4 * wbc);
            #pragma unroll
            for (int j = 0; j < 9; ++j) {
                float4 v4 = ps[j];
                p[4*j] = v4.x; p[4*j+1] = v4.y; p[4*j+2] = v4.z; p[4*j+3] = v4.w;
            }

            float a0 = acc[c][0], a1 = acc[c][1], a2 = acc[c][2], a3 = acc[c][3];
            #pragma unroll
            for (int v = 0; v < KW; ++v) {
                float kv = kk[v];
                a0 = fmaf(kv, p[v],     a0);
                a1 = fmaf(kv, p[v + 1], a1);
                a2 = fmaf(kv, p[v + 2], a2);
                a3 = fmaf(kv, p[v + 3], a3);
            }
            acc[c][0] = a0; acc[c][1] = a1; acc[c][2] = a2; acc[c][3] = a3;
        }

        asm volatile("cp.async.wait_group 0;" ::: "memory");
        __syncthreads();
    }

    // ---------------- 3-way reduction through smem (reuse patch region) ----------------
    float* red = patchS;   // needs 2*128*12 = 3072 words << CSTRIDE*3
    __syncthreads();       // everyone done reading patchS
    if (g > 0) {
        float* dst = red + ((g - 1) * 128 + wg_tid) * 12;
        #pragma unroll
        for (int c = 0; c < 3; ++c)
            #pragma unroll
            for (int j = 0; j < 4; ++j) dst[c * 4 + j] = acc[c][j];
    }
    __syncthreads();

    if (g == 0) {
        const float* p1 = red + wg_tid * 12;
        const float* p2 = red + (128 + wg_tid) * 12;
        const int orow = 4 * hb + oi;
        const int ocol = 128 * bx + 4 * wbc;
        #pragma unroll
        for (int c = 0; c < 3; ++c) {
            float4 r;
            r.x = acc[c][0] + p1[c*4+0] + p2[c*4+0];
            r.y = acc[c][1] + p1[c*4+1] + p2[c*4+1];
            r.z = acc[c][2] + p1[c*4+2] + p2[c*4+2];
            r.w = acc[c][3] + p1[c*4+3] + p2[c*4+3];
            *reinterpret_cast<float4*>(out + (c * IMG + orow) * IMG + ocol) = r;
        }
    }
}

extern "C" void kernel_launch(void* const* d_in, const int* in_sizes, int n_in,
                              void* d_out, int out_size)
{
    const float* img = (const float*)d_in[0];   // (1,3,512,512) fp32
    const float* Kg  = (const float*)d_in[1];   // (1,1089,128,128) fp32
    float* out = (float*)d_out;                 // (1,3,512,512) fp32

    cudaFuncSetAttribute(reblur_kernel,
                         cudaFuncAttributeMaxDynamicSharedMemorySize, SMEM_BYTES);
    dim3 grid(4, 128);
    reblur_kernel<<<grid, 384, SMEM_BYTES>>>(img, Kg, out);
}